// round 9
// baseline (speedup 1.0000x reference)
#include <cuda_runtime.h>

// DCTExtractor: gray = .299R+.587G+.114B; per 8x8 block: D @ blk @ D^T, * mask.
// x: (B,3,512,512) fp32 -> out: (B,1,512,512) fp32. HBM-bound (268 MB min traffic).
//
// v3: persistent grid-stride (296 CTAs x 512 thr), software-pipelined: next
// tile's LDGs issued before current tile's smem/store phase, so DRAM stays
// busy across __syncthreads. Streaming cache hints (no reuse, 268MB > L2).

#define HW 512
#define SPAD 76   // floats per 8x8 block in staging; conflict-free transpose

__global__ __launch_bounds__(512, 2)
void dct_extract_kernel(const float* __restrict__ x,
                        const float* __restrict__ dct,
                        const float* __restrict__ mask,
                        float* __restrict__ out,
                        int ntiles)
{
    __shared__ float s[64 * SPAD];     // 19456 B staging (row-transformed blocks)
    __shared__ float Dh_s[8][4];       // D[l][k], k=0..3 (butterfly half)
    __shared__ float M_s[64];

    const int tid = threadIdx.x;
    if (tid < 64) {
        M_s[tid] = mask[tid];
        if ((tid & 7) < 4) Dh_s[tid >> 3][tid & 7] = dct[tid];
    }
    __syncthreads();

    const size_t plane = (size_t)HW * HW;
    const int stride = gridDim.x;

    // Step-A unit coords: r = row-in-strip, blkA = block along width.
    const int rA   = tid >> 6;
    const int blkA = tid & 63;
    // Step-B unit coords: l = column-in-block, blkB = block along width.
    const int lB   = tid & 7;
    const int blkB = tid >> 3;

    int t = blockIdx.x;

    // ---- Prologue: load tile t (coalesced float4 x 6, streaming) ----
    float4 R0, R1, G0, G1, B0, B1;
    {
        const int b = t >> 6, rowbase = (t & 63) << 3;
        const float* p0 = x + (size_t)b * 3 * plane + (size_t)(rowbase + rA) * HW + blkA * 8;
        R0 = __ldcs(reinterpret_cast<const float4*>(p0));
        R1 = __ldcs(reinterpret_cast<const float4*>(p0 + 4));
        G0 = __ldcs(reinterpret_cast<const float4*>(p0 + plane));
        G1 = __ldcs(reinterpret_cast<const float4*>(p0 + plane + 4));
        B0 = __ldcs(reinterpret_cast<const float4*>(p0 + 2 * plane));
        B1 = __ldcs(reinterpret_cast<const float4*>(p0 + 2 * plane + 4));
    }

    while (true) {
        // ---- Grayscale (consumes raw regs) ----
        float g[8];
        g[0] = fmaf(0.299f, R0.x, fmaf(0.587f, G0.x, 0.114f * B0.x));
        g[1] = fmaf(0.299f, R0.y, fmaf(0.587f, G0.y, 0.114f * B0.y));
        g[2] = fmaf(0.299f, R0.z, fmaf(0.587f, G0.z, 0.114f * B0.z));
        g[3] = fmaf(0.299f, R0.w, fmaf(0.587f, G0.w, 0.114f * B0.w));
        g[4] = fmaf(0.299f, R1.x, fmaf(0.587f, G1.x, 0.114f * B1.x));
        g[5] = fmaf(0.299f, R1.y, fmaf(0.587f, G1.y, 0.114f * B1.y));
        g[6] = fmaf(0.299f, R1.z, fmaf(0.587f, G1.z, 0.114f * B1.z));
        g[7] = fmaf(0.299f, R1.w, fmaf(0.587f, G1.w, 0.114f * B1.w));

        // ---- Prefetch next tile (covers the entire store phase + syncs) ----
        const int t_next = t + stride;
        const bool more = (t_next < ntiles);
        if (more) {
            const int bn = t_next >> 6, rbn = (t_next & 63) << 3;
            const float* pn = x + (size_t)bn * 3 * plane + (size_t)(rbn + rA) * HW + blkA * 8;
            R0 = __ldcs(reinterpret_cast<const float4*>(pn));
            R1 = __ldcs(reinterpret_cast<const float4*>(pn + 4));
            G0 = __ldcs(reinterpret_cast<const float4*>(pn + plane));
            G1 = __ldcs(reinterpret_cast<const float4*>(pn + plane + 4));
            B0 = __ldcs(reinterpret_cast<const float4*>(pn + 2 * plane));
            B1 = __ldcs(reinterpret_cast<const float4*>(pn + 2 * plane + 4));
        }

        // ---- Row-direction DCT (butterfly), stage into padded smem ----
        {
            const float e0 = g[0] + g[7], e1 = g[1] + g[6], e2 = g[2] + g[5], e3 = g[3] + g[4];
            const float o0 = g[0] - g[7], o1 = g[1] - g[6], o2 = g[2] - g[5], o3 = g[3] - g[4];
            float v[8];
#pragma unroll
            for (int h = 0; h < 4; h++) {
                const int le = 2 * h, lo = 2 * h + 1;
                v[le] = fmaf(Dh_s[le][0], e0, fmaf(Dh_s[le][1], e1,
                        fmaf(Dh_s[le][2], e2, Dh_s[le][3] * e3)));
                v[lo] = fmaf(Dh_s[lo][0], o0, fmaf(Dh_s[lo][1], o1,
                        fmaf(Dh_s[lo][2], o2, Dh_s[lo][3] * o3)));
            }
            float* sp = s + blkA * SPAD + rA * 8;
            *reinterpret_cast<float4*>(sp)     = make_float4(v[0], v[1], v[2], v[3]);
            *reinterpret_cast<float4*>(sp + 4) = make_float4(v[4], v[5], v[6], v[7]);
        }
        __syncthreads();

        // ---- Column-direction DCT + mask + coalesced streaming stores ----
        {
            const float* sp = s + blkB * SPAD + lB;
            float tt[8];
#pragma unroll
            for (int p = 0; p < 8; p++) tt[p] = sp[p * 8];

            const float e0 = tt[0] + tt[7], e1 = tt[1] + tt[6], e2 = tt[2] + tt[5], e3 = tt[3] + tt[4];
            const float o0 = tt[0] - tt[7], o1 = tt[1] - tt[6], o2 = tt[2] - tt[5], o3 = tt[3] - tt[4];

            const int b = t >> 6, rowbase = (t & 63) << 3;
            float* op = out + ((size_t)b * HW + rowbase) * HW + blkB * 8 + lB;
#pragma unroll
            for (int h = 0; h < 4; h++) {
                const int ie = 2 * h, io = 2 * h + 1;
                float ae = fmaf(Dh_s[ie][0], e0, fmaf(Dh_s[ie][1], e1,
                           fmaf(Dh_s[ie][2], e2, Dh_s[ie][3] * e3)));
                float ao = fmaf(Dh_s[io][0], o0, fmaf(Dh_s[io][1], o1,
                           fmaf(Dh_s[io][2], o2, Dh_s[io][3] * o3)));
                __stcs(op + (size_t)ie * HW, ae * M_s[ie * 8 + lB]);
                __stcs(op + (size_t)io * HW, ao * M_s[io * 8 + lB]);
            }
        }

        if (!more) break;
        __syncthreads();        // protect smem before next iteration's STS
        t = t_next;
    }
}

extern "C" void kernel_launch(void* const* d_in, const int* in_sizes, int n_in,
                              void* d_out, int out_size)
{
    const float* x    = (const float*)d_in[0];
    const float* dct  = (const float*)d_in[1];
    const float* mask = (const float*)d_in[2];
    float* out = (float*)d_out;

    const int B = in_sizes[0] / (3 * HW * HW);
    const int ntiles = B * (HW / 8);           // 4096 for B=64
    int grid = 2 * 148;                        // 2 CTAs/SM resident, persistent
    if (grid > ntiles) grid = ntiles;
    dct_extract_kernel<<<grid, 512>>>(x, dct, mask, out, ntiles);
}

// round 11
// speedup vs baseline: 1.0007x; 1.0007x over previous
#include <cuda_runtime.h>

// DCTExtractor: gray = .299R+.587G+.114B; per 8x8 block: D @ blk @ D^T, * mask.
// x: (B,3,512,512) fp32 -> out: (B,1,512,512) fp32. HBM-bound (268 MB min traffic).
//
// v3: persistent grid-stride (296 CTAs x 512 thr), software-pipelined: next
// tile's LDGs issued before current tile's smem/store phase, so DRAM stays
// busy across __syncthreads. Streaming cache hints (no reuse, 268MB > L2).

#define HW 512
#define SPAD 76   // floats per 8x8 block in staging; conflict-free transpose

__global__ __launch_bounds__(512, 2)
void dct_extract_kernel(const float* __restrict__ x,
                        const float* __restrict__ dct,
                        const float* __restrict__ mask,
                        float* __restrict__ out,
                        int ntiles)
{
    __shared__ float s[64 * SPAD];     // 19456 B staging (row-transformed blocks)
    __shared__ float Dh_s[8][4];       // D[l][k], k=0..3 (butterfly half)
    __shared__ float M_s[64];

    const int tid = threadIdx.x;
    if (tid < 64) {
        M_s[tid] = mask[tid];
        if ((tid & 7) < 4) Dh_s[tid >> 3][tid & 7] = dct[tid];
    }
    __syncthreads();

    const size_t plane = (size_t)HW * HW;
    const int stride = gridDim.x;

    // Step-A unit coords: r = row-in-strip, blkA = block along width.
    const int rA   = tid >> 6;
    const int blkA = tid & 63;
    // Step-B unit coords: l = column-in-block, blkB = block along width.
    const int lB   = tid & 7;
    const int blkB = tid >> 3;

    int t = blockIdx.x;

    // ---- Prologue: load tile t (coalesced float4 x 6, streaming) ----
    float4 R0, R1, G0, G1, B0, B1;
    {
        const int b = t >> 6, rowbase = (t & 63) << 3;
        const float* p0 = x + (size_t)b * 3 * plane + (size_t)(rowbase + rA) * HW + blkA * 8;
        R0 = __ldcs(reinterpret_cast<const float4*>(p0));
        R1 = __ldcs(reinterpret_cast<const float4*>(p0 + 4));
        G0 = __ldcs(reinterpret_cast<const float4*>(p0 + plane));
        G1 = __ldcs(reinterpret_cast<const float4*>(p0 + plane + 4));
        B0 = __ldcs(reinterpret_cast<const float4*>(p0 + 2 * plane));
        B1 = __ldcs(reinterpret_cast<const float4*>(p0 + 2 * plane + 4));
    }

    while (true) {
        // ---- Grayscale (consumes raw regs) ----
        float g[8];
        g[0] = fmaf(0.299f, R0.x, fmaf(0.587f, G0.x, 0.114f * B0.x));
        g[1] = fmaf(0.299f, R0.y, fmaf(0.587f, G0.y, 0.114f * B0.y));
        g[2] = fmaf(0.299f, R0.z, fmaf(0.587f, G0.z, 0.114f * B0.z));
        g[3] = fmaf(0.299f, R0.w, fmaf(0.587f, G0.w, 0.114f * B0.w));
        g[4] = fmaf(0.299f, R1.x, fmaf(0.587f, G1.x, 0.114f * B1.x));
        g[5] = fmaf(0.299f, R1.y, fmaf(0.587f, G1.y, 0.114f * B1.y));
        g[6] = fmaf(0.299f, R1.z, fmaf(0.587f, G1.z, 0.114f * B1.z));
        g[7] = fmaf(0.299f, R1.w, fmaf(0.587f, G1.w, 0.114f * B1.w));

        // ---- Prefetch next tile (covers the entire store phase + syncs) ----
        const int t_next = t + stride;
        const bool more = (t_next < ntiles);
        if (more) {
            const int bn = t_next >> 6, rbn = (t_next & 63) << 3;
            const float* pn = x + (size_t)bn * 3 * plane + (size_t)(rbn + rA) * HW + blkA * 8;
            R0 = __ldcs(reinterpret_cast<const float4*>(pn));
            R1 = __ldcs(reinterpret_cast<const float4*>(pn + 4));
            G0 = __ldcs(reinterpret_cast<const float4*>(pn + plane));
            G1 = __ldcs(reinterpret_cast<const float4*>(pn + plane + 4));
            B0 = __ldcs(reinterpret_cast<const float4*>(pn + 2 * plane));
            B1 = __ldcs(reinterpret_cast<const float4*>(pn + 2 * plane + 4));
        }

        // ---- Row-direction DCT (butterfly), stage into padded smem ----
        {
            const float e0 = g[0] + g[7], e1 = g[1] + g[6], e2 = g[2] + g[5], e3 = g[3] + g[4];
            const float o0 = g[0] - g[7], o1 = g[1] - g[6], o2 = g[2] - g[5], o3 = g[3] - g[4];
            float v[8];
#pragma unroll
            for (int h = 0; h < 4; h++) {
                const int le = 2 * h, lo = 2 * h + 1;
                v[le] = fmaf(Dh_s[le][0], e0, fmaf(Dh_s[le][1], e1,
                        fmaf(Dh_s[le][2], e2, Dh_s[le][3] * e3)));
                v[lo] = fmaf(Dh_s[lo][0], o0, fmaf(Dh_s[lo][1], o1,
                        fmaf(Dh_s[lo][2], o2, Dh_s[lo][3] * o3)));
            }
            float* sp = s + blkA * SPAD + rA * 8;
            *reinterpret_cast<float4*>(sp)     = make_float4(v[0], v[1], v[2], v[3]);
            *reinterpret_cast<float4*>(sp + 4) = make_float4(v[4], v[5], v[6], v[7]);
        }
        __syncthreads();

        // ---- Column-direction DCT + mask + coalesced streaming stores ----
        {
            const float* sp = s + blkB * SPAD + lB;
            float tt[8];
#pragma unroll
            for (int p = 0; p < 8; p++) tt[p] = sp[p * 8];

            const float e0 = tt[0] + tt[7], e1 = tt[1] + tt[6], e2 = tt[2] + tt[5], e3 = tt[3] + tt[4];
            const float o0 = tt[0] - tt[7], o1 = tt[1] - tt[6], o2 = tt[2] - tt[5], o3 = tt[3] - tt[4];

            const int b = t >> 6, rowbase = (t & 63) << 3;
            float* op = out + ((size_t)b * HW + rowbase) * HW + blkB * 8 + lB;
#pragma unroll
            for (int h = 0; h < 4; h++) {
                const int ie = 2 * h, io = 2 * h + 1;
                float ae = fmaf(Dh_s[ie][0], e0, fmaf(Dh_s[ie][1], e1,
                           fmaf(Dh_s[ie][2], e2, Dh_s[ie][3] * e3)));
                float ao = fmaf(Dh_s[io][0], o0, fmaf(Dh_s[io][1], o1,
                           fmaf(Dh_s[io][2], o2, Dh_s[io][3] * o3)));
                __stcs(op + (size_t)ie * HW, ae * M_s[ie * 8 + lB]);
                __stcs(op + (size_t)io * HW, ao * M_s[io * 8 + lB]);
            }
        }

        if (!more) break;
        __syncthreads();        // protect smem before next iteration's STS
        t = t_next;
    }
}

extern "C" void kernel_launch(void* const* d_in, const int* in_sizes, int n_in,
                              void* d_out, int out_size)
{
    const float* x    = (const float*)d_in[0];
    const float* dct  = (const float*)d_in[1];
    const float* mask = (const float*)d_in[2];
    float* out = (float*)d_out;

    const int B = in_sizes[0] / (3 * HW * HW);
    const int ntiles = B * (HW / 8);           // 4096 for B=64
    int grid = 2 * 148;                        // 2 CTAs/SM resident, persistent
    if (grid > ntiles) grid = ntiles;
    dct_extract_kernel<<<grid, 512>>>(x, dct, mask, out, ntiles);
}

// round 12
// speedup vs baseline: 1.0345x; 1.0337x over previous
#include <cuda_runtime.h>

// DCTExtractor: gray = .299R+.587G+.114B; per 8x8 block: D @ blk @ D^T, * mask.
// x: (B,3,512,512) fp32 -> out: (B,1,512,512) fp32. HBM-bound (268 MB min traffic).
//
// v3: persistent grid-stride (296 CTAs x 512 thr), software-pipelined: next
// tile's LDGs issued before current tile's smem/store phase, so DRAM stays
// busy across __syncthreads. Streaming cache hints (no reuse, 268MB > L2).

#define HW 512
#define SPAD 76   // floats per 8x8 block in staging; conflict-free transpose

__global__ __launch_bounds__(512, 2)
void dct_extract_kernel(const float* __restrict__ x,
                        const float* __restrict__ dct,
                        const float* __restrict__ mask,
                        float* __restrict__ out,
                        int ntiles)
{
    __shared__ float s[64 * SPAD];     // 19456 B staging (row-transformed blocks)
    __shared__ float Dh_s[8][4];       // D[l][k], k=0..3 (butterfly half)
    __shared__ float M_s[64];

    const int tid = threadIdx.x;
    if (tid < 64) {
        M_s[tid] = mask[tid];
        if ((tid & 7) < 4) Dh_s[tid >> 3][tid & 7] = dct[tid];
    }
    __syncthreads();

    const size_t plane = (size_t)HW * HW;
    const int stride = gridDim.x;

    // Step-A unit coords: r = row-in-strip, blkA = block along width.
    const int rA   = tid >> 6;
    const int blkA = tid & 63;
    // Step-B unit coords: l = column-in-block, blkB = block along width.
    const int lB   = tid & 7;
    const int blkB = tid >> 3;

    int t = blockIdx.x;

    // ---- Prologue: load tile t (coalesced float4 x 6, streaming) ----
    float4 R0, R1, G0, G1, B0, B1;
    {
        const int b = t >> 6, rowbase = (t & 63) << 3;
        const float* p0 = x + (size_t)b * 3 * plane + (size_t)(rowbase + rA) * HW + blkA * 8;
        R0 = __ldcs(reinterpret_cast<const float4*>(p0));
        R1 = __ldcs(reinterpret_cast<const float4*>(p0 + 4));
        G0 = __ldcs(reinterpret_cast<const float4*>(p0 + plane));
        G1 = __ldcs(reinterpret_cast<const float4*>(p0 + plane + 4));
        B0 = __ldcs(reinterpret_cast<const float4*>(p0 + 2 * plane));
        B1 = __ldcs(reinterpret_cast<const float4*>(p0 + 2 * plane + 4));
    }

    while (true) {
        // ---- Grayscale (consumes raw regs) ----
        float g[8];
        g[0] = fmaf(0.299f, R0.x, fmaf(0.587f, G0.x, 0.114f * B0.x));
        g[1] = fmaf(0.299f, R0.y, fmaf(0.587f, G0.y, 0.114f * B0.y));
        g[2] = fmaf(0.299f, R0.z, fmaf(0.587f, G0.z, 0.114f * B0.z));
        g[3] = fmaf(0.299f, R0.w, fmaf(0.587f, G0.w, 0.114f * B0.w));
        g[4] = fmaf(0.299f, R1.x, fmaf(0.587f, G1.x, 0.114f * B1.x));
        g[5] = fmaf(0.299f, R1.y, fmaf(0.587f, G1.y, 0.114f * B1.y));
        g[6] = fmaf(0.299f, R1.z, fmaf(0.587f, G1.z, 0.114f * B1.z));
        g[7] = fmaf(0.299f, R1.w, fmaf(0.587f, G1.w, 0.114f * B1.w));

        // ---- Prefetch next tile (covers the entire store phase + syncs) ----
        const int t_next = t + stride;
        const bool more = (t_next < ntiles);
        if (more) {
            const int bn = t_next >> 6, rbn = (t_next & 63) << 3;
            const float* pn = x + (size_t)bn * 3 * plane + (size_t)(rbn + rA) * HW + blkA * 8;
            R0 = __ldcs(reinterpret_cast<const float4*>(pn));
            R1 = __ldcs(reinterpret_cast<const float4*>(pn + 4));
            G0 = __ldcs(reinterpret_cast<const float4*>(pn + plane));
            G1 = __ldcs(reinterpret_cast<const float4*>(pn + plane + 4));
            B0 = __ldcs(reinterpret_cast<const float4*>(pn + 2 * plane));
            B1 = __ldcs(reinterpret_cast<const float4*>(pn + 2 * plane + 4));
        }

        // ---- Row-direction DCT (butterfly), stage into padded smem ----
        {
            const float e0 = g[0] + g[7], e1 = g[1] + g[6], e2 = g[2] + g[5], e3 = g[3] + g[4];
            const float o0 = g[0] - g[7], o1 = g[1] - g[6], o2 = g[2] - g[5], o3 = g[3] - g[4];
            float v[8];
#pragma unroll
            for (int h = 0; h < 4; h++) {
                const int le = 2 * h, lo = 2 * h + 1;
                v[le] = fmaf(Dh_s[le][0], e0, fmaf(Dh_s[le][1], e1,
                        fmaf(Dh_s[le][2], e2, Dh_s[le][3] * e3)));
                v[lo] = fmaf(Dh_s[lo][0], o0, fmaf(Dh_s[lo][1], o1,
                        fmaf(Dh_s[lo][2], o2, Dh_s[lo][3] * o3)));
            }
            float* sp = s + blkA * SPAD + rA * 8;
            *reinterpret_cast<float4*>(sp)     = make_float4(v[0], v[1], v[2], v[3]);
            *reinterpret_cast<float4*>(sp + 4) = make_float4(v[4], v[5], v[6], v[7]);
        }
        __syncthreads();

        // ---- Column-direction DCT + mask + coalesced streaming stores ----
        {
            const float* sp = s + blkB * SPAD + lB;
            float tt[8];
#pragma unroll
            for (int p = 0; p < 8; p++) tt[p] = sp[p * 8];

            const float e0 = tt[0] + tt[7], e1 = tt[1] + tt[6], e2 = tt[2] + tt[5], e3 = tt[3] + tt[4];
            const float o0 = tt[0] - tt[7], o1 = tt[1] - tt[6], o2 = tt[2] - tt[5], o3 = tt[3] - tt[4];

            const int b = t >> 6, rowbase = (t & 63) << 3;
            float* op = out + ((size_t)b * HW + rowbase) * HW + blkB * 8 + lB;
#pragma unroll
            for (int h = 0; h < 4; h++) {
                const int ie = 2 * h, io = 2 * h + 1;
                float ae = fmaf(Dh_s[ie][0], e0, fmaf(Dh_s[ie][1], e1,
                           fmaf(Dh_s[ie][2], e2, Dh_s[ie][3] * e3)));
                float ao = fmaf(Dh_s[io][0], o0, fmaf(Dh_s[io][1], o1,
                           fmaf(Dh_s[io][2], o2, Dh_s[io][3] * o3)));
                __stcs(op + (size_t)ie * HW, ae * M_s[ie * 8 + lB]);
                __stcs(op + (size_t)io * HW, ao * M_s[io * 8 + lB]);
            }
        }

        if (!more) break;
        __syncthreads();        // protect smem before next iteration's STS
        t = t_next;
    }
}

extern "C" void kernel_launch(void* const* d_in, const int* in_sizes, int n_in,
                              void* d_out, int out_size)
{
    const float* x    = (const float*)d_in[0];
    const float* dct  = (const float*)d_in[1];
    const float* mask = (const float*)d_in[2];
    float* out = (float*)d_out;

    const int B = in_sizes[0] / (3 * HW * HW);
    const int ntiles = B * (HW / 8);           // 4096 for B=64
    int grid = 2 * 148;                        // 2 CTAs/SM resident, persistent
    if (grid > ntiles) grid = ntiles;
    dct_extract_kernel<<<grid, 512>>>(x, dct, mask, out, ntiles);
}